// round 1
// baseline (speedup 1.0000x reference)
#include <cuda_runtime.h>
#include <cstdint>

// ---------------------------------------------------------------------------
// EMA Vector-Quantizer, GB300 sm_103a
// Inputs (metadata order): z[16,64,32,32] f32, weight[8192,64] f32,
//                          cluster_size[8192] f32, embed_avg[8192,64] f32
// Output (flat concat):    z_q_out[1048576], loss[1], new_weight[524288],
//                          new_cluster_size[8192], new_embed_avg[524288]
// ---------------------------------------------------------------------------

#define NTOK   16384
#define NCODE  8192
#define DIM    64
#define SPLITS 4
#define CPS    (NCODE / SPLITS)   // codes per split
#define TPB    128                // tokens per block in argmin kernel
#define CHUNK  32                 // codes staged in smem per iteration

#define OFF_ZQ   0
#define OFF_LOSS 1048576
#define OFF_W    1048577
#define OFF_CS   1572865
#define OFF_EA   1581057

static constexpr float DECAY = 0.99f;
static constexpr float OMD   = (float)(1.0 - 0.99);  // 1 - decay
static constexpr float EPS_  = 1e-5f;
static constexpr float BETA_ = 0.25f;

// ---- device scratch (no allocations allowed) ------------------------------
__device__ float g_wsq[NCODE];
__device__ float g_cand_dist[SPLITS * NTOK];
__device__ int   g_cand_idx[SPLITS * NTOK];
__device__ int   g_idx[NTOK];
__device__ float g_loss;
__device__ float g_n;

// ---- packed f32x2 helpers (Blackwell FFMA2 path) --------------------------
__device__ __forceinline__ unsigned long long fma2(unsigned long long a,
                                                   unsigned long long b,
                                                   unsigned long long c) {
    unsigned long long d;
    asm("fma.rn.f32x2 %0, %1, %2, %3;" : "=l"(d) : "l"(a), "l"(b), "l"(c));
    return d;
}
__device__ __forceinline__ unsigned long long add2(unsigned long long a,
                                                   unsigned long long b) {
    unsigned long long d;
    asm("add.rn.f32x2 %0, %1, %2;" : "=l"(d) : "l"(a), "l"(b));
    return d;
}
__device__ __forceinline__ unsigned long long pack2(float a, float b) {
    unsigned long long d;
    asm("mov.b64 %0, {%1, %2};" : "=l"(d) : "f"(a), "f"(b));
    return d;
}
__device__ __forceinline__ float2 unpack2(unsigned long long a) {
    float lo, hi;
    asm("mov.b64 {%0, %1}, %2;" : "=f"(lo), "=f"(hi) : "l"(a));
    return make_float2(lo, hi);
}

// ---------------------------------------------------------------------------
// Kernel 1: prep — wsq per code row, init EMA outputs, zero loss accumulator
// ---------------------------------------------------------------------------
__global__ void prep_kernel(const float* __restrict__ weight,
                            const float* __restrict__ cluster_size,
                            const float* __restrict__ embed_avg,
                            float* __restrict__ out) {
    int i = blockIdx.x * blockDim.x + threadIdx.x;
    if (i < NCODE * DIM) out[OFF_EA + i] = embed_avg[i] * DECAY;
    if (i < NCODE) {
        out[OFF_CS + i] = cluster_size[i] * DECAY;
        const float4* row = reinterpret_cast<const float4*>(weight + (size_t)i * DIM);
        float s = 0.f;
#pragma unroll
        for (int j = 0; j < DIM / 4; j++) {
            float4 v = row[j];
            s += v.x * v.x + v.y * v.y + v.z * v.z + v.w * v.w;
        }
        g_wsq[i] = s;
    }
    if (i == 0) g_loss = 0.f;
}

// ---------------------------------------------------------------------------
// Kernel 2: argmin — each thread owns 1 token (z row packed into 32 f32x2
// registers), scans a 2048-code split; weight chunks staged in SMEM and read
// via broadcast LDS.128. Distance d = wsq[k] - 2*dot(z,w[k]) (zsq dropped —
// constant per token). Strict '<' with ascending k preserves jnp.argmin
// first-minimum tie-breaking.
// ---------------------------------------------------------------------------
__global__ __launch_bounds__(TPB) void argmin_kernel(const float* __restrict__ z,
                                                     const float* __restrict__ weight) {
    const int tb    = blockIdx.x / SPLITS;
    const int split = blockIdx.x % SPLITS;
    const int n  = tb * TPB + threadIdx.x;
    const int b  = n >> 10;
    const int hw = n & 1023;

    // load z row: z[b, d, h, w] = z[(b*64 + d)*1024 + hw]; coalesced per d
    const float* zb = z + (size_t)b * (DIM * 1024) + hw;
    unsigned long long zr[DIM / 2];
#pragma unroll
    for (int d = 0; d < DIM; d += 2) {
        float a = zb[(size_t)d * 1024];
        float c = zb[(size_t)(d + 1) * 1024];
        zr[d / 2] = pack2(a, c);
    }

    __shared__ __align__(16) float sw[CHUNK * DIM];
    __shared__ float ssq[CHUNK];

    const int cbase = split * CPS;
    float best  = 3.4e38f;
    int   bestk = 0;

    for (int ch = 0; ch < CPS; ch += CHUNK) {
        __syncthreads();
        {   // stage CHUNK codes (8KB) into smem, coalesced float4
            const float4* src = reinterpret_cast<const float4*>(
                weight + (size_t)(cbase + ch) * DIM);
            float4* dst = reinterpret_cast<float4*>(sw);
#pragma unroll
            for (int i = threadIdx.x; i < CHUNK * DIM / 4; i += TPB) dst[i] = src[i];
            if (threadIdx.x < CHUNK) ssq[threadIdx.x] = g_wsq[cbase + ch + threadIdx.x];
        }
        __syncthreads();

        for (int c = 0; c < CHUNK; c++) {
            const ulonglong2* wr = reinterpret_cast<const ulonglong2*>(sw + c * DIM);
            unsigned long long a0 = 0ull, a1 = 0ull, a2 = 0ull, a3 = 0ull;
#pragma unroll
            for (int i = 0; i < DIM / 4; i += 2) {  // 16 LDS.128 + 32 FFMA2
                ulonglong2 w0 = wr[i];
                ulonglong2 w1 = wr[i + 1];
                a0 = fma2(zr[2 * i],     w0.x, a0);
                a1 = fma2(zr[2 * i + 1], w0.y, a1);
                a2 = fma2(zr[2 * i + 2], w1.x, a2);
                a3 = fma2(zr[2 * i + 3], w1.y, a3);
            }
            a0 = add2(a0, a1);
            a2 = add2(a2, a3);
            a0 = add2(a0, a2);
            float2 p  = unpack2(a0);
            float dot = p.x + p.y;
            float dist = fmaf(-2.f, dot, ssq[c]);
            if (dist < best) { best = dist; bestk = cbase + ch + c; }
        }
    }
    g_cand_dist[split * NTOK + n] = best;
    g_cand_idx[split * NTOK + n]  = bestk;
}

// ---------------------------------------------------------------------------
// Kernel 3: combine split candidates -> idx; accumulate cluster counts
// ---------------------------------------------------------------------------
__global__ void combine_kernel(float* __restrict__ out) {
    int n = blockIdx.x * blockDim.x + threadIdx.x;
    if (n >= NTOK) return;
    float best = g_cand_dist[n];
    int   bk   = g_cand_idx[n];
#pragma unroll
    for (int s = 1; s < SPLITS; s++) {
        float d2 = g_cand_dist[s * NTOK + n];
        int   k2 = g_cand_idx[s * NTOK + n];
        if (d2 < best) { best = d2; bk = k2; }
    }
    g_idx[n] = bk;
    atomicAdd(&out[OFF_CS + bk], OMD);
}

// ---------------------------------------------------------------------------
// Kernel 4: z_q output (gather, coalesced in hw) + commitment-loss partials
// z and z_q_out share [b,c,h,w] layout, so index i maps directly.
// ---------------------------------------------------------------------------
__global__ void zq_loss_kernel(const float* __restrict__ z,
                               const float* __restrict__ weight,
                               float* __restrict__ out) {
    int i = blockIdx.x * blockDim.x + threadIdx.x;  // [0, 1048576)
    int hw = i & 1023;
    int c  = (i >> 10) & 63;
    int b  = i >> 16;
    int n  = b * 1024 + hw;
    int k  = g_idx[n];
    float wv = __ldg(weight + (size_t)k * DIM + c);
    out[OFF_ZQ + i] = wv;
    float diff = wv - z[i];
    float s = diff * diff;
#pragma unroll
    for (int o = 16; o; o >>= 1) s += __shfl_xor_sync(0xffffffffu, s, o);
    __shared__ float red[8];
    if ((threadIdx.x & 31) == 0) red[threadIdx.x >> 5] = s;
    __syncthreads();
    if (threadIdx.x == 0) {
        float t = 0.f;
#pragma unroll
        for (int j = 0; j < 8; j++) t += red[j];
        atomicAdd(&g_loss, t);
    }
}

// ---------------------------------------------------------------------------
// Kernel 5: EMA embed scatter — warp per token, lanes over dims (coalesced
// atomics within a codebook row)
// ---------------------------------------------------------------------------
__global__ void scatter_kernel(const float* __restrict__ z,
                               float* __restrict__ out) {
    int gw   = (blockIdx.x * blockDim.x + threadIdx.x) >> 5;
    int lane = threadIdx.x & 31;
    if (gw >= NTOK) return;
    int b  = gw >> 10;
    int hw = gw & 1023;
    int k  = g_idx[gw];
    const float* zb = z + (size_t)b * (DIM * 1024) + hw;
    float* dst = out + OFF_EA + (size_t)k * DIM;
#pragma unroll
    for (int d = lane; d < DIM; d += 32) {
        atomicAdd(&dst[d], OMD * zb[(size_t)d * 1024]);
    }
}

// ---------------------------------------------------------------------------
// Kernel 6: n = sum(new_cluster_size); finalize loss scalar
// ---------------------------------------------------------------------------
__global__ void reduce_kernel(float* __restrict__ out) {
    __shared__ float red[32];
    float s = 0.f;
    for (int i = threadIdx.x; i < NCODE; i += blockDim.x) s += out[OFF_CS + i];
#pragma unroll
    for (int o = 16; o; o >>= 1) s += __shfl_xor_sync(0xffffffffu, s, o);
    if ((threadIdx.x & 31) == 0) red[threadIdx.x >> 5] = s;
    __syncthreads();
    if (threadIdx.x == 0) {
        float t = 0.f;
        int nw = blockDim.x / 32;
        for (int j = 0; j < nw; j++) t += red[j];
        g_n = t;
        out[OFF_LOSS] = BETA_ * g_loss / 1048576.f;
    }
}

// ---------------------------------------------------------------------------
// Kernel 7: new_weight = new_embed_avg / smoothed(new_cluster_size)
// ---------------------------------------------------------------------------
__global__ void weight_kernel(float* __restrict__ out) {
    int i = blockIdx.x * blockDim.x + threadIdx.x;
    if (i >= NCODE * DIM) return;
    int k = i >> 6;
    float nn = g_n;
    float cs = out[OFF_CS + k];
    float smoothed = (cs + EPS_) / (nn + NCODE * EPS_) * nn;
    out[OFF_W + i] = out[OFF_EA + i] / smoothed;
}

// ---------------------------------------------------------------------------
extern "C" void kernel_launch(void* const* d_in, const int* in_sizes, int n_in,
                              void* d_out, int out_size) {
    const float* z            = (const float*)d_in[0];
    const float* weight       = (const float*)d_in[1];
    const float* cluster_size = (const float*)d_in[2];
    const float* embed_avg    = (const float*)d_in[3];
    float* out = (float*)d_out;

    prep_kernel<<<(NCODE * DIM + 255) / 256, 256>>>(weight, cluster_size, embed_avg, out);
    argmin_kernel<<<(NTOK / TPB) * SPLITS, TPB>>>(z, weight);
    combine_kernel<<<(NTOK + 255) / 256, 256>>>(out);
    zq_loss_kernel<<<(NTOK * DIM) / 256, 256>>>(z, weight, out);
    scatter_kernel<<<(NTOK * 32) / 256, 256>>>(z, out);
    reduce_kernel<<<1, 1024>>>(out);
    weight_kernel<<<(NCODE * DIM + 255) / 256, 256>>>(out);
}